// round 7
// baseline (speedup 1.0000x reference)
#include <cuda_runtime.h>
#include <cstdint>

#define THREADS 256
#define TILE 32
#define XSTR2 194   // Xs row stride in float2 units (192 + 2 pad)
#define HSTR2 130   // Hs row stride in float2 units (128 + 2 pad)

// ---- shared memory layout (floats) ----
constexpr int OFF_W1 = 0;                 // 192*128 = 24576
constexpr int OFF_W2 = 24576;             // 128*128 = 16384
constexpr int OFF_X  = 40960;             // 32*194*2 = 12416 (duplicated X; H aliases)
constexpr int OFF_RS = 53376;             // 256
constexpr int OFF_RQ = 53632;             // 256
constexpr int OFF_MU = 53888;             // 32
constexpr int OFF_SG = 53920;             // 32
constexpr int SMEM_FLOATS = 53952;        // 215808 bytes

__device__ __forceinline__ unsigned long long packf2(float x, float y) {
    unsigned long long r;
    asm("mov.b64 %0, {%1, %2};" : "=l"(r) : "f"(x), "f"(y));
    return r;
}
__device__ __forceinline__ void unpackf2(unsigned long long v, float& x, float& y) {
    asm("mov.b64 {%0, %1}, %2;" : "=f"(x), "=f"(y) : "l"(v));
}
__device__ __forceinline__ void fma2(unsigned long long& d, unsigned long long a, unsigned long long b) {
    asm("fma.rn.f32x2 %0, %1, %2, %0;" : "+l"(d) : "l"(a), "l"(b));
}
__device__ __forceinline__ float silu(float v) {
    return v / (1.0f + __expf(-v));
}

__global__ void __launch_bounds__(THREADS, 1)
edge_mlp_kernel(const float* __restrict__ src, const float* __restrict__ edg,
                const float* __restrict__ W1,  const float* __restrict__ b1,
                const float* __restrict__ gam, const float* __restrict__ bet,
                const float* __restrict__ W2,  const float* __restrict__ b2,
                float* __restrict__ out, int E, int ntiles)
{
    extern __shared__ float s[];
    float* W1s = s + OFF_W1;
    float* W2s = s + OFF_W2;
    float* Xs  = s + OFF_X;    // duplicated-pair storage; Hs aliases same region
    float* RS  = s + OFF_RS;
    float* RQ  = s + OFF_RQ;
    float* MU  = s + OFF_MU;
    float* SG  = s + OFF_SG;

    const int tid  = threadIdx.x;
    const int warp = tid >> 5;
    const int lane = tid & 31;
    const int lc   = lane & 3;             // col-group within warp
    const int lr   = lane >> 2;            // row index base (0..7)
    const int c4   = warp * 16 + lc * 4;   // 4 output cols

    // rows owned by this thread: lr, lr+8, lr+16, lr+24  (stride-1 across warp
    // lanes -> bank stride 2*XSTR2 mod 32 = 4 -> conflict-free LDS)
    int xb[4], hb[4];
    #pragma unroll
    for (int i = 0; i < 4; i++) {
        xb[i] = 2 * ((lr + 8 * i) * XSTR2);
        hb[i] = 2 * ((lr + 8 * i) * HSTR2);
    }

    // ---- stage weights into SMEM (once per block) ----
    {
        const float4* w1v = reinterpret_cast<const float4*>(W1);
        float4* w1s = reinterpret_cast<float4*>(W1s);
        #pragma unroll
        for (int i = 0; i < (24576 / 4) / THREADS; i++)
            w1s[tid + i * THREADS] = w1v[tid + i * THREADS];
        const float4* w2v = reinterpret_cast<const float4*>(W2);
        float4* w2s = reinterpret_cast<float4*>(W2s);
        #pragma unroll
        for (int i = 0; i < (16384 / 4) / THREADS; i++)
            w2s[tid + i * THREADS] = w2v[tid + i * THREADS];
    }
    // per-thread column constants
    float gg[4], be[4];
    unsigned long long b1p[2], b2p[2];
    {
        float t0 = b1[c4 + 0], t1 = b1[c4 + 1], t2 = b1[c4 + 2], t3 = b1[c4 + 3];
        b1p[0] = packf2(t0, t1); b1p[1] = packf2(t2, t3);
        t0 = b2[c4 + 0]; t1 = b2[c4 + 1]; t2 = b2[c4 + 2]; t3 = b2[c4 + 3];
        b2p[0] = packf2(t0, t1); b2p[1] = packf2(t2, t3);
        #pragma unroll
        for (int j = 0; j < 4; j++) { gg[j] = gam[c4 + j]; be[j] = bet[c4 + j]; }
    }
    __syncthreads();

    for (int tile = blockIdx.x; tile < ntiles; tile += gridDim.x) {
        const int row0 = tile * TILE;

        // ---- load x tile, store DUPLICATED pairs: Xs[r][k] = (x,x) ----
        #pragma unroll
        for (int i = 0; i < 4; i++) {           // src: 1024 float4
            int idx = tid + i * THREADS;
            int r = idx >> 5, c = (idx & 31) << 2;
            int rg = row0 + r; if (rg >= E) rg = E - 1;
            float4 v = *reinterpret_cast<const float4*>(src + (size_t)rg * 128 + c);
            float* d = &Xs[2 * (r * XSTR2 + c)];
            *reinterpret_cast<float4*>(d)     = make_float4(v.x, v.x, v.y, v.y);
            *reinterpret_cast<float4*>(d + 4) = make_float4(v.z, v.z, v.w, v.w);
        }
        #pragma unroll
        for (int i = 0; i < 2; i++) {           // edge: 512 float4
            int idx = tid + i * THREADS;
            int r = idx >> 4, c = (idx & 15) << 2;
            int rg = row0 + r; if (rg >= E) rg = E - 1;
            float4 v = *reinterpret_cast<const float4*>(edg + (size_t)rg * 64 + c);
            float* d = &Xs[2 * (r * XSTR2 + 128 + c)];
            *reinterpret_cast<float4*>(d)     = make_float4(v.x, v.x, v.y, v.y);
            *reinterpret_cast<float4*>(d + 4) = make_float4(v.z, v.z, v.w, v.w);
        }
        __syncthreads();

        // ---- GEMM1: h[32][128] = x[32][192] @ W1 (packed f32x2) ----
        unsigned long long acc[4][2];
        #pragma unroll
        for (int i = 0; i < 4; i++) { acc[i][0] = b1p[0]; acc[i][1] = b1p[1]; }

        #pragma unroll 2
        for (int k = 0; k < 192; k += 2) {
            ulonglong2 wa = *reinterpret_cast<const ulonglong2*>(&W1s[k * 128 + c4]);
            ulonglong2 wb = *reinterpret_cast<const ulonglong2*>(&W1s[(k + 1) * 128 + c4]);
            #pragma unroll
            for (int i = 0; i < 4; i++) {
                ulonglong2 xv = *reinterpret_cast<const ulonglong2*>(&Xs[xb[i] + 2 * k]);
                fma2(acc[i][0], xv.x, wa.x); fma2(acc[i][1], xv.x, wa.y);
                fma2(acc[i][0], xv.y, wb.x); fma2(acc[i][1], xv.y, wb.y);
            }
        }

        float h[4][4];
        #pragma unroll
        for (int i = 0; i < 4; i++) {
            unpackf2(acc[i][0], h[i][0], h[i][1]);
            unpackf2(acc[i][1], h[i][2], h[i][3]);
        }

        // ---- LayerNorm reductions ----
        #pragma unroll
        for (int i = 0; i < 4; i++) {
            float sv = h[i][0] + h[i][1] + h[i][2] + h[i][3];
            float qv = h[i][0]*h[i][0] + h[i][1]*h[i][1] + h[i][2]*h[i][2] + h[i][3]*h[i][3];
            sv += __shfl_xor_sync(0xffffffffu, sv, 1);
            sv += __shfl_xor_sync(0xffffffffu, sv, 2);
            qv += __shfl_xor_sync(0xffffffffu, qv, 1);
            qv += __shfl_xor_sync(0xffffffffu, qv, 2);
            if (lc == 0) { RS[warp * 32 + lr + 8 * i] = sv; RQ[warp * 32 + lr + 8 * i] = qv; }
        }
        __syncthreads();
        if (tid < 32) {
            float ss = 0.f, qq = 0.f;
            #pragma unroll
            for (int w = 0; w < 8; w++) { ss += RS[w * 32 + tid]; qq += RQ[w * 32 + tid]; }
            float mu  = ss * (1.0f / 128.0f);
            float var = qq * (1.0f / 128.0f) - mu * mu;
            MU[tid] = mu;
            SG[tid] = rsqrtf(var + 1e-5f);
        }
        __syncthreads();

        // ---- normalize + SiLU -> duplicated Hs (aliases Xs region) ----
        #pragma unroll
        for (int i = 0; i < 4; i++) {
            float mu = MU[lr + 8 * i], sg = SG[lr + 8 * i];
            float h0 = silu((h[i][0] - mu) * sg * gg[0] + be[0]);
            float h1 = silu((h[i][1] - mu) * sg * gg[1] + be[1]);
            float h2 = silu((h[i][2] - mu) * sg * gg[2] + be[2]);
            float h3 = silu((h[i][3] - mu) * sg * gg[3] + be[3]);
            float* d = &Xs[hb[i] + 2 * c4];
            *reinterpret_cast<float4*>(d)     = make_float4(h0, h0, h1, h1);
            *reinterpret_cast<float4*>(d + 4) = make_float4(h2, h2, h3, h3);
        }
        __syncthreads();

        // ---- GEMM2: o[32][128] = hsilu[32][128] @ W2 ----
        unsigned long long acc2[4][2];
        #pragma unroll
        for (int i = 0; i < 4; i++) { acc2[i][0] = b2p[0]; acc2[i][1] = b2p[1]; }

        #pragma unroll 2
        for (int k = 0; k < 128; k += 2) {
            ulonglong2 wa = *reinterpret_cast<const ulonglong2*>(&W2s[k * 128 + c4]);
            ulonglong2 wb = *reinterpret_cast<const ulonglong2*>(&W2s[(k + 1) * 128 + c4]);
            #pragma unroll
            for (int i = 0; i < 4; i++) {
                ulonglong2 xv = *reinterpret_cast<const ulonglong2*>(&Xs[hb[i] + 2 * k]);
                fma2(acc2[i][0], xv.x, wa.x); fma2(acc2[i][1], xv.x, wa.y);
                fma2(acc2[i][0], xv.y, wb.x); fma2(acc2[i][1], xv.y, wb.y);
            }
        }

        // ---- SiLU + store ----
        #pragma unroll
        for (int i = 0; i < 4; i++) {
            float o0, o1, o2, o3;
            unpackf2(acc2[i][0], o0, o1);
            unpackf2(acc2[i][1], o2, o3);
            float4 t = make_float4(silu(o0), silu(o1), silu(o2), silu(o3));
            int rg = row0 + lr + 8 * i;
            if (rg < E)
                *reinterpret_cast<float4*>(out + (size_t)rg * 128 + c4) = t;
        }

        __syncthreads();   // protect Xs/Hs/RS/RQ before next tile
    }
}

extern "C" void kernel_launch(void* const* d_in, const int* in_sizes, int n_in,
                              void* d_out, int out_size) {
    const float* src = (const float*)d_in[0];
    const float* edg = (const float*)d_in[1];
    const float* W1  = (const float*)d_in[2];
    const float* b1  = (const float*)d_in[3];
    const float* gam = (const float*)d_in[4];
    const float* bet = (const float*)d_in[5];
    const float* W2  = (const float*)d_in[6];
    const float* b2  = (const float*)d_in[7];
    float* out = (float*)d_out;

    int E = in_sizes[0] / 128;
    int ntiles = (E + TILE - 1) / TILE;

    cudaFuncSetAttribute(edge_mlp_kernel,
                         cudaFuncAttributeMaxDynamicSharedMemorySize,
                         SMEM_FLOATS * sizeof(float));

    int grid = ntiles < 152 ? ntiles : 152;
    edge_mlp_kernel<<<grid, THREADS, SMEM_FLOATS * sizeof(float)>>>(
        src, edg, W1, b1, gam, bet, W2, b2, out, E, ntiles);
}

// round 8
// speedup vs baseline: 1.2356x; 1.2356x over previous
#include <cuda_runtime.h>
#include <cstdint>

#define THREADS 128
#define TILE 64
#define XSTR 196   // X row stride in floats (192 + 4); %32 = 4 (bank-offset), %4 = 0 (16B align)
#define HSTR 132   // H row stride in floats (128 + 4); %32 = 4, %4 = 0

// ---- shared memory layout (floats) ----
constexpr int OFF_W1 = 0;                 // 192*128 = 24576
constexpr int OFF_W2 = 24576;             // 128*128 = 16384
constexpr int OFF_X  = 40960;             // 64*196 = 12544 (H: 64*132=8448 aliases this)
constexpr int OFF_RS = 53504;             // 4*64 = 256
constexpr int OFF_RQ = 53760;             // 256
constexpr int OFF_MU = 54016;             // 64
constexpr int OFF_SG = 54080;             // 64
constexpr int SMEM_FLOATS = 54144;        // 216576 bytes

__device__ __forceinline__ unsigned long long packf2(float x, float y) {
    unsigned long long r;
    asm("mov.b64 %0, {%1, %2};" : "=l"(r) : "f"(x), "f"(y));
    return r;
}
__device__ __forceinline__ void unpackf2(unsigned long long v, float& x, float& y) {
    asm("mov.b64 {%0, %1}, %2;" : "=f"(x), "=f"(y) : "l"(v));
}
__device__ __forceinline__ void fma2(unsigned long long& d, unsigned long long a, unsigned long long b) {
    asm("fma.rn.f32x2 %0, %1, %2, %0;" : "+l"(d) : "l"(a), "l"(b));
}
__device__ __forceinline__ float silu(float v) {
    return v / (1.0f + __expf(-v));
}

__global__ void __launch_bounds__(THREADS, 1)
edge_mlp_kernel(const float* __restrict__ src, const float* __restrict__ edg,
                const float* __restrict__ W1,  const float* __restrict__ b1,
                const float* __restrict__ gam, const float* __restrict__ bet,
                const float* __restrict__ W2,  const float* __restrict__ b2,
                float* __restrict__ out, int E, int ntiles)
{
    extern __shared__ float s[];
    float* W1s = s + OFF_W1;
    float* W2s = s + OFF_W2;
    float* Xs  = s + OFF_X;    // H aliases this region after GEMM1
    float* RS  = s + OFF_RS;
    float* RQ  = s + OFF_RQ;
    float* MU  = s + OFF_MU;
    float* SG  = s + OFF_SG;

    const int tid  = threadIdx.x;
    const int warp = tid >> 5;          // 0..3
    const int lane = tid & 31;
    const int rg   = lane >> 2;         // 0..7  : rows {rg+8i}, i=0..7
    const int l3   = lane & 3;          // 0..3
    const int cg   = warp * 4 + l3;     // 0..15 : cols [cg*8, cg*8+8)
    const int c8   = cg * 8;

    // ---- stage weights into SMEM (once per block) ----
    {
        const float4* w1v = reinterpret_cast<const float4*>(W1);
        float4* w1s = reinterpret_cast<float4*>(W1s);
        #pragma unroll
        for (int i = 0; i < (24576 / 4) / THREADS; i++)
            w1s[tid + i * THREADS] = w1v[tid + i * THREADS];
        const float4* w2v = reinterpret_cast<const float4*>(W2);
        float4* w2s = reinterpret_cast<float4*>(W2s);
        #pragma unroll
        for (int i = 0; i < (16384 / 4) / THREADS; i++)
            w2s[tid + i * THREADS] = w2v[tid + i * THREADS];
    }
    // per-thread column constants (8 cols)
    float gg[8], be[8];
    unsigned long long b1p[4], b2p[4];
    #pragma unroll
    for (int j = 0; j < 4; j++) {
        b1p[j] = packf2(b1[c8 + 2 * j], b1[c8 + 2 * j + 1]);
        b2p[j] = packf2(b2[c8 + 2 * j], b2[c8 + 2 * j + 1]);
    }
    #pragma unroll
    for (int j = 0; j < 8; j++) { gg[j] = gam[c8 + j]; be[j] = bet[c8 + j]; }
    __syncthreads();

    for (int tile = blockIdx.x; tile < ntiles; tile += gridDim.x) {
        const int row0 = tile * TILE;

        // ---- load x tile row-major: Xs[r][0:128)=src, [128:192)=edge ----
        #pragma unroll
        for (int i = 0; i < 16; i++) {          // src: 64 rows x 32 float4 = 2048
            int idx = tid + i * THREADS;
            int r = idx >> 5, c = (idx & 31) << 2;
            int rg_ = row0 + r; if (rg_ >= E) rg_ = E - 1;
            float4 v = *reinterpret_cast<const float4*>(src + (size_t)rg_ * 128 + c);
            *reinterpret_cast<float4*>(&Xs[r * XSTR + c]) = v;
        }
        #pragma unroll
        for (int i = 0; i < 8; i++) {           // edge: 64 rows x 16 float4 = 1024
            int idx = tid + i * THREADS;
            int r = idx >> 4, c = (idx & 15) << 2;
            int rg_ = row0 + r; if (rg_ >= E) rg_ = E - 1;
            float4 v = *reinterpret_cast<const float4*>(edg + (size_t)rg_ * 64 + c);
            *reinterpret_cast<float4*>(&Xs[r * XSTR + 128 + c]) = v;
        }
        __syncthreads();

        // ---- GEMM1: h[64][128] = x[64][192] @ W1 ; 8 rows x 8 cols / thread ----
        unsigned long long acc[8][4];
        #pragma unroll
        for (int i = 0; i < 8; i++)
            #pragma unroll
            for (int j = 0; j < 4; j++) acc[i][j] = b1p[j];

        #pragma unroll 2
        for (int kb = 0; kb < 192; kb += 4) {
            float4 xv[8];
            #pragma unroll
            for (int i = 0; i < 8; i++)
                xv[i] = *reinterpret_cast<const float4*>(&Xs[(rg + 8 * i) * XSTR + kb]);
            #pragma unroll
            for (int kk = 0; kk < 4; kk++) {
                const float* wrow = &W1s[(kb + kk) * 128 + c8];
                ulonglong2 wa = *reinterpret_cast<const ulonglong2*>(wrow);
                ulonglong2 wb = *reinterpret_cast<const ulonglong2*>(wrow + 4);
                #pragma unroll
                for (int i = 0; i < 8; i++) {
                    float xs = (kk == 0) ? xv[i].x : (kk == 1) ? xv[i].y
                              : (kk == 2) ? xv[i].z : xv[i].w;
                    unsigned long long d = packf2(xs, xs);
                    fma2(acc[i][0], d, wa.x); fma2(acc[i][1], d, wa.y);
                    fma2(acc[i][2], d, wb.x); fma2(acc[i][3], d, wb.y);
                }
            }
        }

        float h[8][8];
        #pragma unroll
        for (int i = 0; i < 8; i++)
            #pragma unroll
            for (int j = 0; j < 4; j++)
                unpackf2(acc[i][j], h[i][2 * j], h[i][2 * j + 1]);

        // ---- LayerNorm reduce: 16 threads per row (4 lanes in-warp, 4 warps) ----
        #pragma unroll
        for (int i = 0; i < 8; i++) {
            float sv = 0.f, qv = 0.f;
            #pragma unroll
            for (int j = 0; j < 8; j++) { sv += h[i][j]; qv += h[i][j] * h[i][j]; }
            sv += __shfl_xor_sync(0xffffffffu, sv, 1);
            sv += __shfl_xor_sync(0xffffffffu, sv, 2);
            qv += __shfl_xor_sync(0xffffffffu, qv, 1);
            qv += __shfl_xor_sync(0xffffffffu, qv, 2);
            if (l3 == 0) { RS[warp * 64 + rg + 8 * i] = sv; RQ[warp * 64 + rg + 8 * i] = qv; }
        }
        __syncthreads();
        if (tid < 64) {
            float ss = 0.f, qq = 0.f;
            #pragma unroll
            for (int w = 0; w < 4; w++) { ss += RS[w * 64 + tid]; qq += RQ[w * 64 + tid]; }
            float mu  = ss * (1.0f / 128.0f);
            float var = qq * (1.0f / 128.0f) - mu * mu;
            MU[tid] = mu;
            SG[tid] = rsqrtf(var + 1e-5f);
        }
        __syncthreads();

        // ---- normalize + SiLU -> Hs row-major (aliases Xs) ----
        #pragma unroll
        for (int i = 0; i < 8; i++) {
            float mu = MU[rg + 8 * i], sg = SG[rg + 8 * i];
            float hn[8];
            #pragma unroll
            for (int j = 0; j < 8; j++)
                hn[j] = silu((h[i][j] - mu) * sg * gg[j] + be[j]);
            float* d = &Xs[(rg + 8 * i) * HSTR + c8];
            *reinterpret_cast<float4*>(d)     = make_float4(hn[0], hn[1], hn[2], hn[3]);
            *reinterpret_cast<float4*>(d + 4) = make_float4(hn[4], hn[5], hn[6], hn[7]);
        }
        __syncthreads();

        // ---- GEMM2: o[64][128] = hsilu[64][128] @ W2 ----
        unsigned long long acc2[8][4];
        #pragma unroll
        for (int i = 0; i < 8; i++)
            #pragma unroll
            for (int j = 0; j < 4; j++) acc2[i][j] = b2p[j];

        #pragma unroll 2
        for (int kb = 0; kb < 128; kb += 4) {
            float4 xv[8];
            #pragma unroll
            for (int i = 0; i < 8; i++)
                xv[i] = *reinterpret_cast<const float4*>(&Xs[(rg + 8 * i) * HSTR + kb]);
            #pragma unroll
            for (int kk = 0; kk < 4; kk++) {
                const float* wrow = &W2s[(kb + kk) * 128 + c8];
                ulonglong2 wa = *reinterpret_cast<const ulonglong2*>(wrow);
                ulonglong2 wb = *reinterpret_cast<const ulonglong2*>(wrow + 4);
                #pragma unroll
                for (int i = 0; i < 8; i++) {
                    float xs = (kk == 0) ? xv[i].x : (kk == 1) ? xv[i].y
                              : (kk == 2) ? xv[i].z : xv[i].w;
                    unsigned long long d = packf2(xs, xs);
                    fma2(acc2[i][0], d, wa.x); fma2(acc2[i][1], d, wa.y);
                    fma2(acc2[i][2], d, wb.x); fma2(acc2[i][3], d, wb.y);
                }
            }
        }

        // ---- SiLU + store ----
        #pragma unroll
        for (int i = 0; i < 8; i++) {
            int rg_ = row0 + rg + 8 * i;
            if (rg_ < E) {
                float o[8];
                #pragma unroll
                for (int j = 0; j < 4; j++) unpackf2(acc2[i][j], o[2 * j], o[2 * j + 1]);
                float* d = out + (size_t)rg_ * 128 + c8;
                *reinterpret_cast<float4*>(d)     = make_float4(silu(o[0]), silu(o[1]), silu(o[2]), silu(o[3]));
                *reinterpret_cast<float4*>(d + 4) = make_float4(silu(o[4]), silu(o[5]), silu(o[6]), silu(o[7]));
            }
        }

        __syncthreads();   // protect Xs/Hs/RS/RQ before next tile
    }
}

extern "C" void kernel_launch(void* const* d_in, const int* in_sizes, int n_in,
                              void* d_out, int out_size) {
    const float* src = (const float*)d_in[0];
    const float* edg = (const float*)d_in[1];
    const float* W1  = (const float*)d_in[2];
    const float* b1  = (const float*)d_in[3];
    const float* gam = (const float*)d_in[4];
    const float* bet = (const float*)d_in[5];
    const float* W2  = (const float*)d_in[6];
    const float* b2  = (const float*)d_in[7];
    float* out = (float*)d_out;

    int E = in_sizes[0] / 128;
    int ntiles = (E + TILE - 1) / TILE;

    cudaFuncSetAttribute(edge_mlp_kernel,
                         cudaFuncAttributeMaxDynamicSharedMemorySize,
                         SMEM_FLOATS * sizeof(float));

    int grid = ntiles < 152 ? ntiles : 152;
    edge_mlp_kernel<<<grid, THREADS, SMEM_FLOATS * sizeof(float)>>>(
        src, edg, W1, b1, gam, bet, W2, b2, out, E, ntiles);
}

// round 11
// speedup vs baseline: 1.4415x; 1.1667x over previous
#include <cuda_runtime.h>
#include <cstdint>

#define THREADS 256
#define TILE 64
#define XSTR 196   // X row stride in floats (192 + 4); %32=4 bank skew, 16B aligned
#define HSTR 132   // H row stride in floats (128 + 4); %32=4

// ---- shared memory layout (floats) ----
constexpr int OFF_W1 = 0;                 // 192*128 = 24576
constexpr int OFF_W2 = 24576;             // 128*128 = 16384
constexpr int OFF_X  = 40960;             // 64*196 = 12544 (H aliases: 64*132=8448)
constexpr int OFF_RS = 53504;             // 4*64 = 256
constexpr int OFF_RQ = 53760;             // 256
constexpr int OFF_MU = 54016;             // 64
constexpr int OFF_SG = 54080;             // 64
constexpr int SMEM_FLOATS = 54144;        // 216576 bytes

__device__ __forceinline__ unsigned long long packf2(float x, float y) {
    unsigned long long r;
    asm("mov.b64 %0, {%1, %2};" : "=l"(r) : "f"(x), "f"(y));
    return r;
}
__device__ __forceinline__ void unpackf2(unsigned long long v, float& x, float& y) {
    asm("mov.b64 {%0, %1}, %2;" : "=f"(x), "=f"(y) : "l"(v));
}
__device__ __forceinline__ void fma2(unsigned long long& d, unsigned long long a, unsigned long long b) {
    asm("fma.rn.f32x2 %0, %1, %2, %0;" : "+l"(d) : "l"(a), "l"(b));
}
__device__ __forceinline__ float silu(float v) {
    return v / (1.0f + __expf(-v));
}

__global__ void __launch_bounds__(THREADS, 1)
edge_mlp_kernel(const float* __restrict__ src, const float* __restrict__ edg,
                const float* __restrict__ W1,  const float* __restrict__ b1,
                const float* __restrict__ gam, const float* __restrict__ bet,
                const float* __restrict__ W2,  const float* __restrict__ b2,
                float* __restrict__ out, int E, int ntiles)
{
    extern __shared__ float s[];
    float* W1s = s + OFF_W1;
    float* W2s = s + OFF_W2;
    float* Xs  = s + OFF_X;    // H aliases this region after GEMM1
    float* RS  = s + OFF_RS;
    float* RQ  = s + OFF_RQ;
    float* MU  = s + OFF_MU;
    float* SG  = s + OFF_SG;

    const int tid  = threadIdx.x;
    const int warp = tid >> 5;              // 0..7
    const int lane = tid & 31;
    const int rg   = lane >> 2;             // 0..7
    const int l3   = lane & 3;              // 0..3
    const int wp   = warp >> 1;             // warp-pair 0..3 (column super-group)
    const int rb   = (warp & 1) * 8 + rg;   // row base 0..15; rows rb+16i, i=0..3
    const int c8   = (wp * 4 + l3) * 8;     // 8 output cols

    // ---- stage weights into SMEM (once per block) ----
    {
        const float4* w1v = reinterpret_cast<const float4*>(W1);
        float4* w1s = reinterpret_cast<float4*>(W1s);
        #pragma unroll
        for (int i = 0; i < (24576 / 4) / THREADS; i++)
            w1s[tid + i * THREADS] = w1v[tid + i * THREADS];
        const float4* w2v = reinterpret_cast<const float4*>(W2);
        float4* w2s = reinterpret_cast<float4*>(W2s);
        #pragma unroll
        for (int i = 0; i < (16384 / 4) / THREADS; i++)
            w2s[tid + i * THREADS] = w2v[tid + i * THREADS];
    }
    // per-thread column constants (8 cols)
    float gg[8], be[8];
    unsigned long long b1p[4], b2p[4];
    #pragma unroll
    for (int j = 0; j < 4; j++) {
        b1p[j] = packf2(b1[c8 + 2 * j], b1[c8 + 2 * j + 1]);
        b2p[j] = packf2(b2[c8 + 2 * j], b2[c8 + 2 * j + 1]);
    }
    #pragma unroll
    for (int j = 0; j < 8; j++) { gg[j] = gam[c8 + j]; be[j] = bet[c8 + j]; }
    __syncthreads();

    for (int tile = blockIdx.x; tile < ntiles; tile += gridDim.x) {
        const int row0 = tile * TILE;

        // ---- load x tile row-major: Xs[r][0:128)=src, [128:192)=edge ----
        #pragma unroll
        for (int i = 0; i < 8; i++) {           // src: 64 rows x 32 float4 = 2048
            int idx = tid + i * THREADS;
            int r = idx >> 5, c = (idx & 31) << 2;
            int r_ = row0 + r; if (r_ >= E) r_ = E - 1;
            float4 v = *reinterpret_cast<const float4*>(src + (size_t)r_ * 128 + c);
            *reinterpret_cast<float4*>(&Xs[r * XSTR + c]) = v;
        }
        #pragma unroll
        for (int i = 0; i < 4; i++) {           // edge: 64 rows x 16 float4 = 1024
            int idx = tid + i * THREADS;
            int r = idx >> 4, c = (idx & 15) << 2;
            int r_ = row0 + r; if (r_ >= E) r_ = E - 1;
            float4 v = *reinterpret_cast<const float4*>(edg + (size_t)r_ * 64 + c);
            *reinterpret_cast<float4*>(&Xs[r * XSTR + 128 + c]) = v;
        }
        __syncthreads();

        // ---- GEMM1: h[64][128] = x[64][192] @ W1 ; 4 rows x 8 cols / thread ----
        unsigned long long acc[4][4];
        #pragma unroll
        for (int i = 0; i < 4; i++)
            #pragma unroll
            for (int j = 0; j < 4; j++) acc[i][j] = b1p[j];

        #pragma unroll 2
        for (int kb = 0; kb < 192; kb += 4) {
            float4 xv[4];
            #pragma unroll
            for (int i = 0; i < 4; i++)
                xv[i] = *reinterpret_cast<const float4*>(&Xs[(rb + 16 * i) * XSTR + kb]);
            #pragma unroll
            for (int kk = 0; kk < 4; kk++) {
                const float* wrow = &W1s[(kb + kk) * 128 + c8];
                ulonglong2 wa = *reinterpret_cast<const ulonglong2*>(wrow);
                ulonglong2 wb = *reinterpret_cast<const ulonglong2*>(wrow + 4);
                #pragma unroll
                for (int i = 0; i < 4; i++) {
                    float xs = (kk == 0) ? xv[i].x : (kk == 1) ? xv[i].y
                              : (kk == 2) ? xv[i].z : xv[i].w;
                    unsigned long long d = packf2(xs, xs);
                    fma2(acc[i][0], d, wa.x); fma2(acc[i][1], d, wa.y);
                    fma2(acc[i][2], d, wb.x); fma2(acc[i][3], d, wb.y);
                }
            }
        }

        float h[4][8];
        #pragma unroll
        for (int i = 0; i < 4; i++)
            #pragma unroll
            for (int j = 0; j < 4; j++)
                unpackf2(acc[i][j], h[i][2 * j], h[i][2 * j + 1]);

        // ---- LayerNorm reduce: 16 threads per row (4 l3-lanes x 4 warp-pairs) ----
        #pragma unroll
        for (int i = 0; i < 4; i++) {
            float sv = 0.f, qv = 0.f;
            #pragma unroll
            for (int j = 0; j < 8; j++) { sv += h[i][j]; qv += h[i][j] * h[i][j]; }
            sv += __shfl_xor_sync(0xffffffffu, sv, 1);
            sv += __shfl_xor_sync(0xffffffffu, sv, 2);
            qv += __shfl_xor_sync(0xffffffffu, qv, 1);
            qv += __shfl_xor_sync(0xffffffffu, qv, 2);
            if (l3 == 0) {
                int r = rb + 16 * i;
                RS[wp * 64 + r] = sv;
                RQ[wp * 64 + r] = qv;
            }
        }
        __syncthreads();
        if (tid < 64) {
            float ss = 0.f, qq = 0.f;
            #pragma unroll
            for (int g = 0; g < 4; g++) { ss += RS[g * 64 + tid]; qq += RQ[g * 64 + tid]; }
            float mu  = ss * (1.0f / 128.0f);
            float var = qq * (1.0f / 128.0f) - mu * mu;
            MU[tid] = mu;
            SG[tid] = rsqrtf(var + 1e-5f);
        }
        __syncthreads();

        // ---- normalize + SiLU -> Hs row-major (aliases Xs) ----
        #pragma unroll
        for (int i = 0; i < 4; i++) {
            int r = rb + 16 * i;
            float mu = MU[r], sg = SG[r];
            float hn[8];
            #pragma unroll
            for (int j = 0; j < 8; j++)
                hn[j] = silu((h[i][j] - mu) * sg * gg[j] + be[j]);
            float* d = &Xs[r * HSTR + c8];
            *reinterpret_cast<float4*>(d)     = make_float4(hn[0], hn[1], hn[2], hn[3]);
            *reinterpret_cast<float4*>(d + 4) = make_float4(hn[4], hn[5], hn[6], hn[7]);
        }
        __syncthreads();

        // ---- GEMM2: o[64][128] = hsilu[64][128] @ W2 ----
        unsigned long long acc2[4][4];
        #pragma unroll
        for (int i = 0; i < 4; i++)
            #pragma unroll
            for (int j = 0; j < 4; j++) acc2[i][j] = b2p[j];

        #pragma unroll 2
        for (int kb = 0; kb < 128; kb += 4) {
            float4 xv[4];
            #pragma unroll
            for (int i = 0; i < 4; i++)
                xv[i] = *reinterpret_cast<const float4*>(&Xs[(rb + 16 * i) * HSTR + kb]);
            #pragma unroll
            for (int kk = 0; kk < 4; kk++) {
                const float* wrow = &W2s[(kb + kk) * 128 + c8];
                ulonglong2 wa = *reinterpret_cast<const ulonglong2*>(wrow);
                ulonglong2 wb = *reinterpret_cast<const ulonglong2*>(wrow + 4);
                #pragma unroll
                for (int i = 0; i < 4; i++) {
                    float xs = (kk == 0) ? xv[i].x : (kk == 1) ? xv[i].y
                              : (kk == 2) ? xv[i].z : xv[i].w;
                    unsigned long long d = packf2(xs, xs);
                    fma2(acc2[i][0], d, wa.x); fma2(acc2[i][1], d, wa.y);
                    fma2(acc2[i][2], d, wb.x); fma2(acc2[i][3], d, wb.y);
                }
            }
        }

        // ---- SiLU + store ----
        #pragma unroll
        for (int i = 0; i < 4; i++) {
            int r_ = row0 + rb + 16 * i;
            if (r_ < E) {
                float o[8];
                #pragma unroll
                for (int j = 0; j < 4; j++) unpackf2(acc2[i][j], o[2 * j], o[2 * j + 1]);
                float* d = out + (size_t)r_ * 128 + c8;
                *reinterpret_cast<float4*>(d)     = make_float4(silu(o[0]), silu(o[1]), silu(o[2]), silu(o[3]));
                *reinterpret_cast<float4*>(d + 4) = make_float4(silu(o[4]), silu(o[5]), silu(o[6]), silu(o[7]));
            }
        }

        __syncthreads();   // protect Xs/Hs/RS/RQ before next tile
    }
}

extern "C" void kernel_launch(void* const* d_in, const int* in_sizes, int n_in,
                              void* d_out, int out_size) {
    const float* src = (const float*)d_in[0];
    const float* edg = (const float*)d_in[1];
    const float* W1  = (const float*)d_in[2];
    const float* b1  = (const float*)d_in[3];
    const float* gam = (const float*)d_in[4];
    const float* bet = (const float*)d_in[5];
    const float* W2  = (const float*)d_in[6];
    const float* b2  = (const float*)d_in[7];
    float* out = (float*)d_out;

    int E = in_sizes[0] / 128;
    int ntiles = (E + TILE - 1) / TILE;

    cudaFuncSetAttribute(edge_mlp_kernel,
                         cudaFuncAttributeMaxDynamicSharedMemorySize,
                         SMEM_FLOATS * sizeof(float));

    int grid = ntiles < 152 ? ntiles : 152;
    edge_mlp_kernel<<<grid, THREADS, SMEM_FLOATS * sizeof(float)>>>(
        src, edg, W1, b1, gam, bet, W2, b2, out, E, ntiles);
}